// round 1
// baseline (speedup 1.0000x reference)
#include <cuda_runtime.h>
#include <cstdint>

#define DD 128
#define M_EDGES 800000
#define TILE_M 128
#define NBLOCKS (M_EDGES / TILE_M)   // 6250, exact
#define AS_STRIDE 132
#define SMEM_FLOATS (2 * 128 * AS_STRIDE + 128 + 128)
#define SMEM_BYTES (SMEM_FLOATS * 4)

// Transposed + tf32-rounded weights: g_Wt[d*128 + k] = tf32(W[k][d]), d in [0,256)
__device__ float g_Wt[256 * 128];

__device__ __forceinline__ uint32_t f32_to_tf32(float v) {
    uint32_t u;
    asm("cvt.rna.tf32.f32 %0, %1;" : "=r"(u) : "f"(v));
    return u;
}

__global__ void transpose_w_kernel(const float* __restrict__ W) {
    int idx = blockIdx.x * blockDim.x + threadIdx.x;
    if (idx >= 256 * 128) return;
    int d = idx >> 7;      // 0..255
    int k = idx & 127;     // 0..127
    float v = W[k * 256 + d];
    g_Wt[d * 128 + k] = __uint_as_float(f32_to_tf32(v));
}

// out[m][k] = sum_d X[m][d] * W[k][d(+128)] + b[k]
// CTA tile: 128 edges x 128 outputs, K = 256 in two 128-phases.
// 256 threads = 8 warps arranged 4 (M) x 2 (N); each warp: 32 rows x 64 cols
// via m16n8k8 tf32 mma (2 m-tiles x 8 n-tiles).
__global__ void __launch_bounds__(256, 1) msg_gemm_kernel(
    const float* __restrict__ H,
    const float* __restrict__ E,
    const int*   __restrict__ heads,
    const float* __restrict__ bias,
    float*       __restrict__ out)
{
    extern __shared__ float smem[];
    float* As     = smem;                       // 128 x 132
    float* Bs     = smem + 128 * AS_STRIDE;     // 128 x 132 (Bs[d][n])
    float* bias_s = Bs + 128 * AS_STRIDE;       // 128
    int*   heads_s = (int*)(bias_s + 128);      // 128

    const int tid  = threadIdx.x;
    const int block_m = blockIdx.x * TILE_M;

    if (tid < 128) {
        bias_s[tid]  = bias[tid];
        heads_s[tid] = heads[block_m + tid];
    }
    __syncthreads();

    const int warp   = tid >> 5;
    const int lane   = tid & 31;
    const int warp_m = warp >> 1;        // 0..3 -> row offset warp_m*32
    const int warp_n = warp & 1;         // 0..1 -> col offset warp_n*64
    const int g = lane >> 2;             // 0..7
    const int t = lane & 3;              // 0..3

    float acc[2][8][4];
    #pragma unroll
    for (int mt = 0; mt < 2; mt++)
        #pragma unroll
        for (int nt = 0; nt < 8; nt++)
            #pragma unroll
            for (int i = 0; i < 4; i++)
                acc[mt][nt][i] = 0.0f;

    // A-load mapping: 8 threads per row, 16 floats (4 float4) per thread
    const int a_r    = tid >> 3;          // 0..31 (row within group of 32)
    const int a_cseg = (tid & 7) * 16;    // column start

    #pragma unroll 1
    for (int phase = 0; phase < 2; phase++) {
        // ---- Load A tile: 128 rows x 128 cols, tf32-rounded ----
        #pragma unroll
        for (int p = 0; p < 4; p++) {
            int row = a_r + p * 32;
            const float* src = (phase == 0)
                ? (H + (size_t)heads_s[row] * DD)
                : (E + (size_t)(block_m + row) * DD);
            #pragma unroll
            for (int i = 0; i < 4; i++) {
                float4 v = *(const float4*)(src + a_cseg + i * 4);
                float* dst = &As[row * AS_STRIDE + a_cseg + i * 4];
                dst[0] = __uint_as_float(f32_to_tf32(v.x));
                dst[1] = __uint_as_float(f32_to_tf32(v.y));
                dst[2] = __uint_as_float(f32_to_tf32(v.z));
                dst[3] = __uint_as_float(f32_to_tf32(v.w));
            }
        }
        // ---- Load B tile: Bs[d][n] = Wt[(phase*128+d)][n] (already tf32) ----
        {
            const float* wsrc = g_Wt + phase * 128 * 128;
            #pragma unroll
            for (int i4 = tid; i4 < 4096; i4 += 256) {
                int d  = i4 >> 5;
                int n4 = (i4 & 31) * 4;
                float4 v = *(const float4*)(wsrc + d * 128 + n4);
                *(float4*)(&Bs[d * AS_STRIDE + n4]) = v;
            }
        }
        __syncthreads();

        // ---- Compute: 16 k-steps of m16n8k8 ----
        #pragma unroll
        for (int ks = 0; ks < 16; ks++) {
            const int k = ks * 8;
            uint32_t afrag[2][4];
            #pragma unroll
            for (int mt = 0; mt < 2; mt++) {
                int row0 = warp_m * 32 + mt * 16 + g;
                afrag[mt][0] = __float_as_uint(As[(row0    ) * AS_STRIDE + k + t    ]);
                afrag[mt][1] = __float_as_uint(As[(row0 + 8) * AS_STRIDE + k + t    ]);
                afrag[mt][2] = __float_as_uint(As[(row0    ) * AS_STRIDE + k + t + 4]);
                afrag[mt][3] = __float_as_uint(As[(row0 + 8) * AS_STRIDE + k + t + 4]);
            }
            uint32_t bfrag[8][2];
            #pragma unroll
            for (int nt = 0; nt < 8; nt++) {
                int col = warp_n * 64 + nt * 8 + g;
                bfrag[nt][0] = __float_as_uint(Bs[(k + t    ) * AS_STRIDE + col]);
                bfrag[nt][1] = __float_as_uint(Bs[(k + t + 4) * AS_STRIDE + col]);
            }
            #pragma unroll
            for (int mt = 0; mt < 2; mt++) {
                #pragma unroll
                for (int nt = 0; nt < 8; nt++) {
                    asm volatile(
                        "mma.sync.aligned.m16n8k8.row.col.f32.tf32.tf32.f32 "
                        "{%0,%1,%2,%3}, {%4,%5,%6,%7}, {%8,%9}, {%0,%1,%2,%3};\n"
                        : "+f"(acc[mt][nt][0]), "+f"(acc[mt][nt][1]),
                          "+f"(acc[mt][nt][2]), "+f"(acc[mt][nt][3])
                        : "r"(afrag[mt][0]), "r"(afrag[mt][1]),
                          "r"(afrag[mt][2]), "r"(afrag[mt][3]),
                          "r"(bfrag[nt][0]), "r"(bfrag[nt][1]));
                }
            }
        }
        __syncthreads();
    }

    // ---- Epilogue: add bias, store fp32 ----
    #pragma unroll
    for (int mt = 0; mt < 2; mt++) {
        int row0 = block_m + warp_m * 32 + mt * 16 + g;
        #pragma unroll
        for (int nt = 0; nt < 8; nt++) {
            int col = warp_n * 64 + nt * 8 + t * 2;
            float2 bv = *(const float2*)(&bias_s[col]);
            float2 v0, v1;
            v0.x = acc[mt][nt][0] + bv.x;
            v0.y = acc[mt][nt][1] + bv.y;
            v1.x = acc[mt][nt][2] + bv.x;
            v1.y = acc[mt][nt][3] + bv.y;
            *(float2*)(&out[(size_t)row0 * DD + col])       = v0;
            *(float2*)(&out[(size_t)(row0 + 8) * DD + col]) = v1;
        }
    }
}

extern "C" void kernel_launch(void* const* d_in, const int* in_sizes, int n_in,
                              void* d_out, int out_size) {
    const float* H     = (const float*)d_in[0];
    const float* E     = (const float*)d_in[1];
    const int*   heads = (const int*)d_in[2];
    // d_in[3] = queries (unused)
    const float* W     = (const float*)d_in[4];
    const float* b     = (const float*)d_in[5];
    float* out = (float*)d_out;

    cudaFuncSetAttribute(msg_gemm_kernel,
                         cudaFuncAttributeMaxDynamicSharedMemorySize, SMEM_BYTES);

    transpose_w_kernel<<<128, 256>>>(W);
    msg_gemm_kernel<<<NBLOCKS, 256, SMEM_BYTES>>>(H, E, heads, b, out);
}

// round 3
// speedup vs baseline: 1.2635x; 1.2635x over previous
#include <cuda_runtime.h>
#include <cstdint>

#define NBLOCKS 6250
#define SROW 68                       // padded floats per A row (conflict-free LDS)
#define ABUF (128 * SROW)             // floats per A buffer
#define SMEM_FLOATS (2 * ABUF + 128)
#define SMEM_BYTES (SMEM_FLOATS * 4)

// B fragments pre-baked for mma.m16n8k8.tf32, laid out so each thread's
// per-kstep fetch is 4 coalesced LDG.128:
// g_Bfrag[(((wn*32 + ks)*32 + lane)*16) + nt*2 + j] = tf32(W[wn*64+nt*8+g][ks*8+t+4j])
__device__ float g_Bfrag[32768];      // 128 KB, L2-resident

__device__ __forceinline__ uint32_t f32_to_tf32(float v) {
    uint32_t u; asm("cvt.rna.tf32.f32 %0, %1;" : "=r"(u) : "f"(v)); return u;
}

__global__ void prep_b_kernel(const float* __restrict__ W) {
    int i = blockIdx.x * 256 + threadIdx.x;       // 0..32767
    int wn   = i >> 14;
    int rem  = i & 16383;
    int ks   = rem >> 9;
    int rem2 = rem & 511;
    int lane = rem2 >> 4;
    int idx  = rem2 & 15;
    int nt = idx >> 1, j = idx & 1;
    int gg = lane >> 2, tt = lane & 3;
    int n = wn * 64 + nt * 8 + gg;
    int k = ks * 8 + tt + 4 * j;
    g_Bfrag[i] = __uint_as_float(f32_to_tf32(W[n * 256 + k]));
}

__device__ __forceinline__ uint32_t smem_u32(const void* p) {
    uint32_t a;
    asm("{ .reg .u64 t; cvta.to.shared.u64 t, %1; cvt.u32.u64 %0, t; }" : "=r"(a) : "l"(p));
    return a;
}
__device__ __forceinline__ void cp16(uint32_t dst, const float* src) {
    asm volatile("cp.async.cg.shared.global [%0], [%1], 16;" :: "r"(dst), "l"(src));
}
__device__ __forceinline__ void mma8(float* acc, uint32_t a0, uint32_t a1,
                                     uint32_t a2, uint32_t a3,
                                     uint32_t b0, uint32_t b1) {
    asm volatile(
        "mma.sync.aligned.m16n8k8.row.col.f32.tf32.tf32.f32 "
        "{%0,%1,%2,%3}, {%4,%5,%6,%7}, {%8,%9}, {%0,%1,%2,%3};\n"
        : "+f"(acc[0]), "+f"(acc[1]), "+f"(acc[2]), "+f"(acc[3])
        : "r"(a0), "r"(a1), "r"(a2), "r"(a3), "r"(b0), "r"(b1));
}

// CTA: 128 edges x 128 outputs. 128 threads = 4 warps (2M x 2N), warp tile 64x64.
// K=256 in four 64-chunks; A double-buffered via cp.async; B fragments via LDG.
__global__ void __launch_bounds__(128, 2) msg_mma_kernel(
    const float* __restrict__ H,
    const float* __restrict__ E,
    const int*   __restrict__ heads,
    const float* __restrict__ bias,
    float*       __restrict__ out)
{
    extern __shared__ __align__(16) float smem_f[];
    float* bias_s = smem_f + 2 * ABUF;
    const uint32_t s_abase = smem_u32(smem_f);

    const int tid  = threadIdx.x;
    const int warp = tid >> 5;
    const int lane = tid & 31;
    const int warp_m = warp >> 1;       // 0..1 -> rows warp_m*64
    const int warp_n = warp & 1;        // 0..1 -> cols warp_n*64
    const int g = lane >> 2;            // 0..7
    const int t = lane & 3;             // 0..3
    const int block_m = blockIdx.x * 128;

    bias_s[tid] = bias[tid];
    const int   my_head = heads[block_m + tid];
    const float* srcH = H + (size_t)my_head * 128;
    const float* srcE = E + (size_t)(block_m + tid) * 128;

    float acc[2][8][4];
    #pragma unroll
    for (int mt = 0; mt < 2; mt++)
        #pragma unroll
        for (int nt = 0; nt < 8; nt++)
            #pragma unroll
            for (int i = 0; i < 4; i++) acc[mt][nt][i] = 0.0f;
    // NOTE: warp tile is 64x64 -> mt runs over 4 sub-tiles of 16 rows; we split
    // acc as [4][8][4] via two halves to keep arrays literal:
    float acc2[2][8][4];
    #pragma unroll
    for (int mt = 0; mt < 2; mt++)
        #pragma unroll
        for (int nt = 0; nt < 8; nt++)
            #pragma unroll
            for (int i = 0; i < 4; i++) acc2[mt][nt][i] = 0.0f;

    // ---- prefetch chunk c into buffer c&1 ----
    auto prefetch = [&](int c) {
        const float* src = (c < 2) ? (srcH + c * 64) : (srcE + (c - 2) * 64);
        uint32_t dst = s_abase + (uint32_t)(((c & 1) * ABUF + tid * SROW) * 4);
        #pragma unroll
        for (int i = 0; i < 16; i++) cp16(dst + i * 16, src + i * 4);
        asm volatile("cp.async.commit_group;" ::: "memory");
    };

    prefetch(0);
    prefetch(1);

    #pragma unroll 1
    for (int c = 0; c < 4; c++) {
        if (c == 3) asm volatile("cp.async.wait_group 0;" ::: "memory");
        else        asm volatile("cp.async.wait_group 1;" ::: "memory");
        __syncthreads();

        const float* Abuf = smem_f + (c & 1) * ABUF;
        #pragma unroll
        for (int ksl = 0; ksl < 8; ksl++) {
            const int ks = c * 8 + ksl;
            const int kl = ksl * 8;
            const float4* bp =
                (const float4*)(g_Bfrag + (((warp_n * 32 + ks) * 32 + lane) << 4));
            float4 bv0 = bp[0], bv1 = bp[1], bv2 = bp[2], bv3 = bp[3];
            uint32_t bf[8][2] = {
                {__float_as_uint(bv0.x), __float_as_uint(bv0.y)},
                {__float_as_uint(bv0.z), __float_as_uint(bv0.w)},
                {__float_as_uint(bv1.x), __float_as_uint(bv1.y)},
                {__float_as_uint(bv1.z), __float_as_uint(bv1.w)},
                {__float_as_uint(bv2.x), __float_as_uint(bv2.y)},
                {__float_as_uint(bv2.z), __float_as_uint(bv2.w)},
                {__float_as_uint(bv3.x), __float_as_uint(bv3.y)},
                {__float_as_uint(bv3.z), __float_as_uint(bv3.w)}};
            #pragma unroll
            for (int mt = 0; mt < 4; mt++) {
                const int row0 = warp_m * 64 + mt * 16 + g;
                uint32_t a0 = f32_to_tf32(Abuf[row0 * SROW + kl + t]);
                uint32_t a1 = f32_to_tf32(Abuf[(row0 + 8) * SROW + kl + t]);
                uint32_t a2 = f32_to_tf32(Abuf[row0 * SROW + kl + t + 4]);
                uint32_t a3 = f32_to_tf32(Abuf[(row0 + 8) * SROW + kl + t + 4]);
                float* arow = (mt < 2) ? acc[mt][0] : acc2[mt - 2][0];
                #pragma unroll
                for (int nt = 0; nt < 8; nt++)
                    mma8(arow + nt * 4, a0, a1, a2, a3, bf[nt][0], bf[nt][1]);
            }
        }
        if (c < 2) {
            __syncthreads();
            prefetch(c + 2);
        }
    }

    // ---- Epilogue: +bias, fp32 stores ----
    #pragma unroll
    for (int mt = 0; mt < 4; mt++) {
        const float* arow = (mt < 2) ? acc[mt][0] : acc2[mt - 2][0];
        const int row0 = block_m + warp_m * 64 + mt * 16 + g;
        #pragma unroll
        for (int nt = 0; nt < 8; nt++) {
            const int col = warp_n * 64 + nt * 8 + t * 2;
            float2 bv = *(const float2*)(bias_s + col);
            float2 v0, v1;
            v0.x = arow[nt * 4 + 0] + bv.x;
            v0.y = arow[nt * 4 + 1] + bv.y;
            v1.x = arow[nt * 4 + 2] + bv.x;
            v1.y = arow[nt * 4 + 3] + bv.y;
            *(float2*)(out + (size_t)row0 * 128 + col)       = v0;
            *(float2*)(out + (size_t)(row0 + 8) * 128 + col) = v1;
        }
    }
}

extern "C" void kernel_launch(void* const* d_in, const int* in_sizes, int n_in,
                              void* d_out, int out_size) {
    const float* H     = (const float*)d_in[0];
    const float* E     = (const float*)d_in[1];
    const int*   heads = (const int*)d_in[2];
    // d_in[3] = queries (unused)
    const float* W     = (const float*)d_in[4];
    const float* b     = (const float*)d_in[5];
    float* out = (float*)d_out;

    cudaFuncSetAttribute(msg_mma_kernel,
                         cudaFuncAttributeMaxDynamicSharedMemorySize, SMEM_BYTES);

    prep_b_kernel<<<128, 256>>>(W);
    msg_mma_kernel<<<NBLOCKS, 128, SMEM_BYTES>>>(H, E, heads, b, out);
}

// round 4
// speedup vs baseline: 1.6874x; 1.3355x over previous
#include <cuda_runtime.h>
#include <cuda_fp16.h>
#include <cstdint>

#define NBLOCKS 6250
#define SROW 72                       // padded floats per A row (LDS.64 conflict-free)
#define ABUF (128 * SROW)             // floats per A buffer
#define SMEM_FLOATS (2 * ABUF + 128)
#define SMEM_BYTES (SMEM_FLOATS * 4)

// fp16 B fragments for mma.m16n8k16, laid out so each thread's per-k16-step
// fetch is 4 coalesced LDG.128:
// g_Bf16[(((wn*16 + ks)*32 + lane)*16) + nt*2 + j]
//   = half2(W[wn*64+nt*8+g][ks*16+2t+8j], W[...][ks*16+2t+8j+1])
__device__ uint32_t g_Bf16[16384];    // 64 KB, L1/L2-resident

__global__ void prep_b16(const float* __restrict__ W) {
    int i = blockIdx.x * 256 + threadIdx.x;   // 0..16383
    int wn   = i >> 13;
    int rem  = i & 8191;
    int ks   = rem >> 9;
    int rem2 = rem & 511;
    int lane = rem2 >> 4;
    int idx  = rem2 & 15;
    int nt = idx >> 1, j = idx & 1;
    int g = lane >> 2, t = lane & 3;
    int n = wn * 64 + nt * 8 + g;
    int k = ks * 16 + 2 * t + 8 * j;
    __half2 h = __floats2half2_rn(W[n * 256 + k], W[n * 256 + k + 1]);
    g_Bf16[i] = *(uint32_t*)&h;
}

__device__ __forceinline__ uint32_t smem_u32(const void* p) {
    uint32_t a;
    asm("{ .reg .u64 t; cvta.to.shared.u64 t, %1; cvt.u32.u64 %0, t; }" : "=r"(a) : "l"(p));
    return a;
}
__device__ __forceinline__ void cp16(uint32_t dst, const float* src) {
    asm volatile("cp.async.cg.shared.global [%0], [%1], 16;" :: "r"(dst), "l"(src));
}
__device__ __forceinline__ uint32_t pack_h2(float2 v) {
    __half2 h = __floats2half2_rn(v.x, v.y);
    return *(uint32_t*)&h;
}
__device__ __forceinline__ void mma16(float* acc, uint32_t a0, uint32_t a1,
                                      uint32_t a2, uint32_t a3,
                                      uint32_t b0, uint32_t b1) {
    asm volatile(
        "mma.sync.aligned.m16n8k16.row.col.f32.f16.f16.f32 "
        "{%0,%1,%2,%3}, {%4,%5,%6,%7}, {%8,%9}, {%0,%1,%2,%3};\n"
        : "+f"(acc[0]), "+f"(acc[1]), "+f"(acc[2]), "+f"(acc[3])
        : "r"(a0), "r"(a1), "r"(a2), "r"(a3), "r"(b0), "r"(b1));
}

// CTA: 128 edges x 128 outputs. 128 threads = 4 warps (2M x 2N), warp tile 64x64.
// K=256 in four 64-chunks; A (fp32) double-buffered via cp.async; B fp16
// fragments via LDG; fragments converted fp32->fp16 at use.
__global__ void __launch_bounds__(128, 2) msg_mma_kernel(
    const float* __restrict__ H,
    const float* __restrict__ E,
    const int*   __restrict__ heads,
    const float* __restrict__ bias,
    float*       __restrict__ out)
{
    extern __shared__ __align__(16) float smem_f[];
    float* bias_s = smem_f + 2 * ABUF;
    const uint32_t s_abase = smem_u32(smem_f);

    const int tid  = threadIdx.x;
    const int warp = tid >> 5;
    const int lane = tid & 31;
    const int warp_m = warp >> 1;       // 0..1 -> rows warp_m*64
    const int warp_n = warp & 1;        // 0..1 -> cols warp_n*64
    const int g = lane >> 2;            // 0..7
    const int t = lane & 3;             // 0..3
    const int block_m = blockIdx.x * 128;

    bias_s[tid] = bias[tid];
    const int   my_head = heads[block_m + tid];
    const float* srcH = H + (size_t)my_head * 128;
    const float* srcE = E + (size_t)(block_m + tid) * 128;

    float acc[2][8][4];
    float acc2[2][8][4];
    #pragma unroll
    for (int mt = 0; mt < 2; mt++)
        #pragma unroll
        for (int nt = 0; nt < 8; nt++)
            #pragma unroll
            for (int i = 0; i < 4; i++) { acc[mt][nt][i] = 0.0f; acc2[mt][nt][i] = 0.0f; }

    // ---- prefetch K-chunk c (64 floats per row) into buffer c&1 ----
    auto prefetch = [&](int c) {
        const float* src = (c < 2) ? (srcH + c * 64) : (srcE + (c - 2) * 64);
        uint32_t dst = s_abase + (uint32_t)(((c & 1) * ABUF + tid * SROW) * 4);
        #pragma unroll
        for (int i = 0; i < 16; i++) cp16(dst + i * 16, src + i * 4);
        asm volatile("cp.async.commit_group;" ::: "memory");
    };

    prefetch(0);
    prefetch(1);

    #pragma unroll 1
    for (int c = 0; c < 4; c++) {
        if (c == 3) asm volatile("cp.async.wait_group 0;" ::: "memory");
        else        asm volatile("cp.async.wait_group 1;" ::: "memory");
        __syncthreads();

        const float* Abuf = smem_f + (c & 1) * ABUF;
        #pragma unroll
        for (int ksl = 0; ksl < 4; ksl++) {       // 4 x k16 per 64-chunk
            const int ks = c * 4 + ksl;           // global k16 step
            const int kl2 = ksl * 16 + 2 * t;     // fragment k base within chunk
            // ---- B fragments: 4 x LDG.128, coalesced, L1-hot ----
            const uint4* bp = (const uint4*)g_Bf16 + ((warp_n * 16 + ks) * 32 + lane) * 4;
            uint4 q0 = bp[0], q1 = bp[1], q2 = bp[2], q3 = bp[3];
            uint32_t bf[8][2] = {
                {q0.x, q0.y}, {q0.z, q0.w},
                {q1.x, q1.y}, {q1.z, q1.w},
                {q2.x, q2.y}, {q2.z, q2.w},
                {q3.x, q3.y}, {q3.z, q3.w}};
            #pragma unroll
            for (int mt = 0; mt < 4; mt++) {
                const int row0 = warp_m * 64 + mt * 16 + g;
                float2 p0 = *(const float2*)(Abuf + row0 * SROW + kl2);
                float2 p1 = *(const float2*)(Abuf + (row0 + 8) * SROW + kl2);
                float2 p2 = *(const float2*)(Abuf + row0 * SROW + kl2 + 8);
                float2 p3 = *(const float2*)(Abuf + (row0 + 8) * SROW + kl2 + 8);
                uint32_t a0 = pack_h2(p0);
                uint32_t a1 = pack_h2(p1);
                uint32_t a2 = pack_h2(p2);
                uint32_t a3 = pack_h2(p3);
                float* arow = (mt < 2) ? acc[mt][0] : acc2[mt - 2][0];
                #pragma unroll
                for (int nt = 0; nt < 8; nt++)
                    mma16(arow + nt * 4, a0, a1, a2, a3, bf[nt][0], bf[nt][1]);
            }
        }
        if (c < 2) {
            __syncthreads();
            prefetch(c + 2);
        }
    }

    // ---- Epilogue: +bias, fp32 stores ----
    #pragma unroll
    for (int mt = 0; mt < 4; mt++) {
        const float* arow = (mt < 2) ? acc[mt][0] : acc2[mt - 2][0];
        const int row0 = block_m + warp_m * 64 + mt * 16 + g;
        #pragma unroll
        for (int nt = 0; nt < 8; nt++) {
            const int col = warp_n * 64 + nt * 8 + t * 2;
            float2 bv = *(const float2*)(bias_s + col);
            float2 v0, v1;
            v0.x = arow[nt * 4 + 0] + bv.x;
            v0.y = arow[nt * 4 + 1] + bv.y;
            v1.x = arow[nt * 4 + 2] + bv.x;
            v1.y = arow[nt * 4 + 3] + bv.y;
            *(float2*)(out + (size_t)row0 * 128 + col)       = v0;
            *(float2*)(out + (size_t)(row0 + 8) * 128 + col) = v1;
        }
    }
}

extern "C" void kernel_launch(void* const* d_in, const int* in_sizes, int n_in,
                              void* d_out, int out_size) {
    const float* H     = (const float*)d_in[0];
    const float* E     = (const float*)d_in[1];
    const int*   heads = (const int*)d_in[2];
    // d_in[3] = queries (unused)
    const float* W     = (const float*)d_in[4];
    const float* b     = (const float*)d_in[5];
    float* out = (float*)d_out;

    cudaFuncSetAttribute(msg_mma_kernel,
                         cudaFuncAttributeMaxDynamicSharedMemorySize, SMEM_BYTES);

    prep_b16<<<64, 256>>>(W);
    msg_mma_kernel<<<NBLOCKS, 128, SMEM_BYTES>>>(H, E, heads, b, out);
}